// round 8
// baseline (speedup 1.0000x reference)
#include <cuda_runtime.h>
#include <math.h>

#define S_TOT 65536
#define CDIM 128
typedef unsigned long long ull;

// ---------------- scratch ----------------------------------------------------
__device__ float g_mean[S_TOT];
__device__ float g_rstd[S_TOT];
__device__ float g_qkv[768u * S_TOT];        // q[0:256] k[256:512] v[512:768]
__device__ float g_aout[8u * S_TOT * 32u];   // [bh][query][c]
__device__ float g_qpd[8*32*16];
__device__ float g_qph[8*32*64];
__device__ float g_qpw[8*32*64];
__device__ float g_kpd[8*32*16];
__device__ float g_kph[8*32*64];
__device__ float g_kpw[8*32*64];
__device__ int   g_idxD[8*4];
__device__ int   g_idxH[8*8];
__device__ float g_kf[8*256*32];
__device__ float g_vf[8*256*32];

// ---------------- f32x2 helpers ----------------------------------------------
__device__ __forceinline__ ull ffma2(ull a, ull b, ull c){
  ull d; asm("fma.rn.f32x2 %0, %1, %2, %3;" : "=l"(d) : "l"(a), "l"(b), "l"(c)); return d;
}
__device__ __forceinline__ ull fmul2(ull a, ull b){
  ull d; asm("mul.rn.f32x2 %0, %1, %2;" : "=l"(d) : "l"(a), "l"(b)); return d;
}
__device__ __forceinline__ ull fadd2(ull a, ull b){
  ull d; asm("add.rn.f32x2 %0, %1, %2;" : "=l"(d) : "l"(a), "l"(b)); return d;
}
__device__ __forceinline__ ull dup2(float x){
  unsigned r = __float_as_uint(x);
  ull d; asm("mov.b64 %0, {%1, %2};" : "=l"(d) : "r"(r), "r"(r)); return d;
}
__device__ __forceinline__ ull pack2(float x, float y){
  ull d; asm("mov.b64 %0, {%1, %2};" : "=l"(d) : "r"(__float_as_uint(x)), "r"(__float_as_uint(y))); return d;
}
__device__ __forceinline__ float2 unpack2(ull v){
  unsigned lo, hi; asm("mov.b64 {%0, %1}, %2;" : "=r"(lo), "=r"(hi) : "l"(v));
  return make_float2(__uint_as_float(lo), __uint_as_float(hi));
}
__device__ __forceinline__ float ex2f(float x){
  float r; asm("ex2.approx.f32 %0, %1;" : "=f"(r) : "f"(x)); return r;
}

__device__ __forceinline__ float warp_sum(float v){
  #pragma unroll
  for (int o=16;o;o>>=1) v += __shfl_xor_sync(0xffffffffu, v, o);
  return v;
}

// ---------------- 1) LayerNorm stats -----------------------------------------
__global__ void k_ln_stats(const float* __restrict__ x){
  int s = blockIdx.x*blockDim.x + threadIdx.x;
  float sum=0.f, sq=0.f;
  #pragma unroll 8
  for (int c=0;c<CDIM;c++){
    float v = x[(size_t)c*S_TOT + s];
    sum += v; sq += v*v;
  }
  float m = sum*(1.f/128.f);
  float var = sq*(1.f/128.f) - m*m;
  g_mean[s] = m;
  g_rstd[s] = 1.f/sqrtf(var + 1e-5f);
}

// ---------------- 2/12) SGEMM: 128x256 tile, 256 thr, 8x16/thread, f32x2 -----
// (exact R2 configuration — proven 888.6us baseline)
template<int KDIM, int MODE>
__global__ void __launch_bounds__(256) k_gemm(
    const float* __restrict__ A, const float* __restrict__ Bx,
    float* __restrict__ Cx, const float* __restrict__ gg,
    const float* __restrict__ bb, const float* __restrict__ bias)
{
  const float* B = (MODE==0) ? Bx : g_aout;
  float* C = (MODE==0) ? g_qkv : Cx;
  __shared__ __align__(16) float As[2][8][128];
  __shared__ __align__(16) float Bs[2][8][256];
  __shared__ __align__(16) float NormS[16][256];
  int t = threadIdx.x;
  int m0 = blockIdx.y*128, n0 = blockIdx.x*256;
  int tx = t & 15, ty = t >> 4;

  int lar = t >> 1, lak = (t & 1) * 4;     // A loader: row, k-quad
  int lbk = t >> 5, lbc = (t & 31) * 4;    // B loader: k-row, col base

  float4 mean4[2], rstd4[2];
  if (MODE==0){
    #pragma unroll
    for (int h=0;h<2;h++){
      mean4[h] = *(const float4*)&g_mean[n0 + lbc + h*128];
      rstd4[h] = *(const float4*)&g_rstd[n0 + lbc + h*128];
    }
  }

  ull acc[8][8];
  #pragma unroll
  for (int i=0;i<8;i++)
    #pragma unroll
    for (int j=0;j<8;j++) acc[i][j] = 0ull;

  const int NS = KDIM/8;
  {
    float4 a4 = *(const float4*)(A + (size_t)(m0+lar)*KDIM + lak);
    As[0][lak+0][lar]=a4.x; As[0][lak+1][lar]=a4.y;
    As[0][lak+2][lar]=a4.z; As[0][lak+3][lar]=a4.w;
    float gk=1.f, bk=0.f;
    if (MODE==0){ gk = gg[lbk]; bk = bb[lbk]; }
    #pragma unroll
    for (int h=0;h<2;h++){
      float4 b4 = *(const float4*)(B + (size_t)lbk*S_TOT + n0 + lbc + h*128);
      if (MODE==0){
        b4.x = (b4.x-mean4[h].x)*rstd4[h].x*gk + bk;
        b4.y = (b4.y-mean4[h].y)*rstd4[h].y*gk + bk;
        b4.z = (b4.z-mean4[h].z)*rstd4[h].z*gk + bk;
        b4.w = (b4.w-mean4[h].w)*rstd4[h].w*gk + bk;
      }
      *(float4*)&Bs[0][lbk][lbc + h*128] = b4;
    }
  }
  __syncthreads();
  int st = 0;
  for (int ks=0; ks<NS; ks++){
    float4 a4n; float4 b4n[2];
    bool more = (ks+1 < NS);
    if (more){
      int k0 = (ks+1)*8;
      a4n = *(const float4*)(A + (size_t)(m0+lar)*KDIM + k0 + lak);
      float gk=1.f, bk=0.f;
      if (MODE==0){ gk = gg[k0+lbk]; bk = bb[k0+lbk]; }
      #pragma unroll
      for (int h=0;h<2;h++){
        float4 b4 = *(const float4*)(B + (size_t)(k0+lbk)*S_TOT + n0 + lbc + h*128);
        if (MODE==0){
          b4.x = (b4.x-mean4[h].x)*rstd4[h].x*gk + bk;
          b4.y = (b4.y-mean4[h].y)*rstd4[h].y*gk + bk;
          b4.z = (b4.z-mean4[h].z)*rstd4[h].z*gk + bk;
          b4.w = (b4.w-mean4[h].w)*rstd4[h].w*gk + bk;
        }
        b4n[h] = b4;
      }
    }
    #pragma unroll
    for (int kk=0;kk<8;kk++){
      float4 av0 = *(const float4*)&As[st][kk][ty*8];
      float4 av1 = *(const float4*)&As[st][kk][ty*8+4];
      float a[8] = {av0.x,av0.y,av0.z,av0.w,av1.x,av1.y,av1.z,av1.w};
      ull b2[8];
      #pragma unroll
      for (int c=0;c<4;c++){
        ulonglong2 bp = *(const ulonglong2*)&Bs[st][kk][tx*4 + c*64];
        b2[c*2] = bp.x; b2[c*2+1] = bp.y;
      }
      #pragma unroll
      for (int i=0;i<8;i++){
        ull da = dup2(a[i]);
        #pragma unroll
        for (int j=0;j<8;j++) acc[i][j] = ffma2(da, b2[j], acc[i][j]);
      }
    }
    if (more){
      int ns = st^1;
      As[ns][lak+0][lar]=a4n.x; As[ns][lak+1][lar]=a4n.y;
      As[ns][lak+2][lar]=a4n.z; As[ns][lak+3][lar]=a4n.w;
      *(float4*)&Bs[ns][lbk][lbc]       = b4n[0];
      *(float4*)&Bs[ns][lbk][lbc + 128] = b4n[1];
      __syncthreads();
      st = ns;
    }
  }

  if (MODE==0 && m0 < 512){
    ull ss2[8];
    #pragma unroll
    for (int j=0;j<8;j++){
      ull s2 = 0ull;
      #pragma unroll
      for (int i=0;i<8;i++) s2 = ffma2(acc[i][j], acc[i][j], s2);
      ss2[j] = s2;
    }
    __syncthreads();
    #pragma unroll
    for (int j=0;j<8;j++){
      int col = tx*4 + (j>>1)*64 + (j&1)*2;
      *(ull*)&NormS[ty][col] = ss2[j];
    }
    __syncthreads();
    int g4 = (ty>>2)*4;
    #pragma unroll
    for (int j=0;j<8;j++){
      int col = tx*4 + (j>>1)*64 + (j&1)*2;
      ull n2 = *(const ull*)&NormS[g4+0][col];
      n2 = fadd2(n2, *(const ull*)&NormS[g4+1][col]);
      n2 = fadd2(n2, *(const ull*)&NormS[g4+2][col]);
      n2 = fadd2(n2, *(const ull*)&NormS[g4+3][col]);
      float2 nf = unpack2(n2);
      float f0 = 1.f/fmaxf(sqrtf(nf.x), 1e-12f);
      float f1 = 1.f/fmaxf(sqrtf(nf.y), 1e-12f);
      ull fv = pack2(f0, f1);
      #pragma unroll
      for (int i=0;i<8;i++) acc[i][j] = fmul2(acc[i][j], fv);
    }
  }

  #pragma unroll
  for (int i=0;i<8;i++){
    int m = m0 + ty*8 + i;
    float bo = (MODE==1) ? bias[m] : 0.f;
    #pragma unroll
    for (int c=0;c<4;c++){
      float2 p0 = unpack2(acc[i][c*2]);
      float2 p1 = unpack2(acc[i][c*2+1]);
      float4 o = make_float4(p0.x+bo, p0.y+bo, p1.x+bo, p1.y+bo);
      *(float4*)(C + (size_t)m*S_TOT + n0 + tx*4 + c*64) = o;
    }
  }
}

// ---------------- 4) probes --------------------------------------------------
__global__ void k_probes(){
  int bh = blockIdx.x >> 5, c = blockIdx.x & 31;
  int t = threadIdx.x, lane = t & 31;
  const float* qp = g_qkv + (size_t)(bh*32+c)*S_TOT;
  const float* kp = g_qkv + (size_t)(256+bh*32+c)*S_TOT;
  __shared__ float sqd[16], skd[16], sqh[64], sqw[64];
  if (t<64){ sqh[t]=0.f; sqw[t]=0.f; }
  if (t<16){ sqd[t]=0.f; skd[t]=0.f; }
  __syncthreads();
  float qW = 0.f;
  float qH[8];
  #pragma unroll
  for (int i=0;i<8;i++) qH[i]=0.f;
  #pragma unroll 1
  for (int m=0;m<16;m++){
    float qD=0.f, kD=0.f;
    #pragma unroll
    for (int i2=0;i2<8;i2++){
      int s = m*4096 + i2*512 + t;
      float qv = fabsf(qp[s]);
      float kv = fabsf(kp[s]);
      qD += qv; kD += kv; qW += qv; qH[i2] += qv;
    }
    qD = warp_sum(qD); kD = warp_sum(kD);
    if (lane==0){ atomicAdd(&sqd[m], qD); atomicAdd(&skd[m], kD); }
  }
  int hb = t >> 6;
  #pragma unroll
  for (int i2=0;i2<8;i2++){
    float v = warp_sum(qH[i2]);
    if (lane==0) atomicAdd(&sqh[i2*8 + hb], v);
  }
  atomicAdd(&sqw[t & 63], qW);
  __syncthreads();
  if (t<16){ g_qpd[(bh*32+c)*16 + t] = sqd[t]; g_kpd[(bh*32+c)*16 + t] = skd[t]; }
  if (t<64){ g_qph[(bh*32+c)*64 + t] = sqh[t]; g_qpw[(bh*32+c)*64 + t] = sqw[t]; }
}

// ---------------- 6) k probe over h (+ fused top-kD, publishes g_idxD) ------
__global__ void k_kprobe_h(){
  int bh = blockIdx.x>>5, c = blockIdx.x&31;
  int t = threadIdx.x, lane = t&31;
  const float* kp = g_qkv + (size_t)(256+bh*32+c)*S_TOT;
  __shared__ float sh[64];
  __shared__ float scD[16];
  __shared__ int sd[4];
  if (t<64) sh[t]=0.f;
  if (t < 32){
    float qv[16], kv[16];
    const float* qb = g_qpd + (bh*32+t)*16;
    const float* kb = g_kpd + (bh*32+t)*16;
    #pragma unroll
    for (int d=0;d<16;d++){ qv[d]=qb[d]; kv[d]=kb[d]; }
    #pragma unroll
    for (int d=0;d<16;d++){
      float v = warp_sum(qv[d]*kv[d]);
      if (t==0) scD[d]=v;
    }
    if (t==0){
      unsigned used=0;
      for (int r=0;r<4;r++){
        float best=-3.4e38f; int bi=0;
        for (int d=0;d<16;d++) if(!((used>>d)&1u) && scD[d]>best){best=scD[d];bi=d;}
        used|=1u<<bi; sd[r]=bi;
      }
    }
  }
  __syncthreads();
  if (c==0 && t<4) g_idxD[bh*4+t]=sd[t];
  float acc[8];
  #pragma unroll
  for (int i=0;i<8;i++) acc[i]=0.f;
  #pragma unroll 1
  for (int di=0; di<4; di++){
    int d = sd[di];
    #pragma unroll
    for (int i2=0;i2<8;i2++){
      int s = d*4096 + i2*512 + t;
      acc[i2] += fabsf(kp[s]);
    }
  }
  int hb = t>>6;
  #pragma unroll
  for (int i2=0;i2<8;i2++){
    float v = warp_sum(acc[i2]);
    if (lane==0) atomicAdd(&sh[i2*8+hb], v);
  }
  __syncthreads();
  if (t<64) g_kph[(bh*32+c)*64+t] = sh[t];
}

// ---------------- 8) k probe over w (+ fused top-kH, publishes g_idxH) ------
__global__ void k_kprobe_w(){
  int bh = blockIdx.x>>5, c = blockIdx.x&31;
  int t = threadIdx.x;
  const float* kp = g_qkv + (size_t)(256+bh*32+c)*S_TOT;
  __shared__ float sw[64];
  __shared__ float scH[64];
  __shared__ int sd[4], shh[8];
  if (t<64) sw[t]=0.f;
  if (t<4)  sd[t]=g_idxD[bh*4+t];
  {
    int w = t>>5, lane = t&31;
    const float* qb = g_qph + (bh*32+lane)*64;
    const float* kb = g_kph + (bh*32+lane)*64;
    #pragma unroll
    for (int i=0;i<8;i++){
      int d = w*8+i;
      float v = warp_sum(qb[d]*kb[d]);
      if (lane==0) scH[d]=v;
    }
  }
  __syncthreads();
  if (t==0){
    unsigned long long used=0ull;
    for (int r=0;r<8;r++){
      float best=-3.4e38f; int bi=0;
      for (int d=0;d<64;d++) if(!((used>>d)&1ull) && scH[d]>best){best=scH[d];bi=d;}
      used|=1ull<<bi; shh[r]=bi;
    }
  }
  __syncthreads();
  if (c==0 && t<8) g_idxH[bh*8+t]=shh[t];
  float acc = 0.f;
  int r = t>>6, w = t&63;
  #pragma unroll
  for (int it=0; it<8; it++){
    int combo = r + it*4;
    int di = combo>>3, hi = combo&7;
    int s = sd[di]*4096 + shh[hi]*64 + w;
    acc += fabsf(kp[s]);
  }
  atomicAdd(&sw[w], acc);
  __syncthreads();
  if (t<64) g_kpw[(bh*32+c)*64+t] = sw[t];
}

// ---------------- 10) gather pruned K/V (+ fused top-kW, local) --------------
__global__ void k_gather(){
  int bh = blockIdx.y;
  int t = threadIdx.x;
  __shared__ float scW[64];
  __shared__ int sd[4], sh8[8], sw8[8];
  if (t<4) sd[t]=g_idxD[bh*4+t];
  if (t<8) sh8[t]=g_idxH[bh*8+t];
  {
    int w = t>>5, lane = t&31;
    const float* qb = g_qpw + (bh*32+lane)*64;
    const float* kb = g_kpw + (bh*32+lane)*64;
    #pragma unroll
    for (int i=0;i<8;i++){
      int d = w*8+i;
      float v = warp_sum(qb[d]*kb[d]);
      if (lane==0) scW[d]=v;
    }
  }
  __syncthreads();
  if (t==0){
    unsigned long long used=0ull;
    for (int r=0;r<8;r++){
      float best=-3.4e38f; int bi=0;
      for (int d=0;d<64;d++) if(!((used>>d)&1ull) && scW[d]>best){best=scW[d];bi=d;}
      used|=1ull<<bi; sw8[r]=bi;
    }
  }
  __syncthreads();
  int j = blockIdx.x*8 + (t>>5);
  int c = t & 31;
  int di = j>>6, hi = (j>>3)&7, wi = j&7;
  int s = sd[di]*4096 + sh8[hi]*64 + sw8[wi];
  g_kf[(bh*256+j)*32 + c] = g_qkv[(size_t)(256+bh*32+c)*S_TOT + s];
  g_vf[(bh*256+j)*32 + c] = g_qkv[(size_t)(512+bh*32+c)*S_TOT + s];
}

// ---------------- 11) attention: 256 thr, 1 query/thread, 2 CTAs/SM ----------
__global__ void __launch_bounds__(256, 2) k_attn(){
  extern __shared__ float smem[];
  float* sk = smem;            // 256*32
  float* sv = smem + 8192;     // 256*32
  int bh = blockIdx.y, t = threadIdx.x;
  const float4* kf4 = (const float4*)(g_kf + (size_t)bh*8192);
  const float4* vf4 = (const float4*)(g_vf + (size_t)bh*8192);
  #pragma unroll
  for (int i=0;i<8;i++){
    ((float4*)sk)[t + i*256] = kf4[t + i*256];
    ((float4*)sv)[t + i*256] = vf4[t + i*256];
  }
  __syncthreads();
  const float LOG2E = 1.4426950408889634f;
  int s0 = blockIdx.x*256 + t;
  ull q0[16];
  #pragma unroll
  for (int c=0;c<16;c++){
    const float* p = g_qkv + (size_t)(bh*32 + 2*c)*S_TOT;
    q0[c] = pack2(p[s0]*LOG2E, p[S_TOT + s0]*LOG2E);
  }
  ull o0[16];
  #pragma unroll
  for (int c=0;c<16;c++) o0[c]=0ull;
  float l0=0.f;
  #pragma unroll 2
  for (int j=0;j<256;j++){
    const ulonglong2* kp = (const ulonglong2*)(sk + j*32);
    ull sA0=0ull,sA1=0ull;
    #pragma unroll
    for (int u=0;u<8;u++){
      ulonglong2 x = kp[u];
      sA0 = ffma2(q0[2*u],   x.x, sA0);
      sA1 = ffma2(q0[2*u+1], x.y, sA1);
    }
    float2 fa = unpack2(fadd2(sA0,sA1));
    float p0 = ex2f(fa.x + fa.y);
    l0 += p0;
    ull pd0 = dup2(p0);
    const ulonglong2* vp = (const ulonglong2*)(sv + j*32);
    #pragma unroll
    for (int u=0;u<8;u++){
      ulonglong2 x = vp[u];
      o0[2*u]   = ffma2(pd0, x.x, o0[2*u]);
      o0[2*u+1] = ffma2(pd0, x.y, o0[2*u+1]);
    }
  }
  ull d0 = dup2(1.f/l0);
  float4* ob0 = (float4*)(g_aout + ((size_t)bh*S_TOT + (size_t)s0)*32u);
  #pragma unroll
  for (int u=0;u<8;u++){
    float2 a = unpack2(fmul2(o0[2*u], d0));
    float2 b = unpack2(fmul2(o0[2*u+1], d0));
    ob0[u] = make_float4(a.x, a.y, b.x, b.y);
  }
}

// ---------------- host ------------------------------------------------------
extern "C" void kernel_launch(void* const* d_in, const int* in_sizes, int n_in,
                              void* d_out, int out_size) {
  (void)in_sizes; (void)n_in; (void)out_size;
  const float* x     = (const float*)d_in[0];
  const float* g     = (const float*)d_in[1];
  const float* b     = (const float*)d_in[2];
  const float* wqkv  = (const float*)d_in[3];
  const float* wout  = (const float*)d_in[4];
  const float* bout  = (const float*)d_in[5];
  float* out = (float*)d_out;

  k_ln_stats<<<S_TOT/256, 256>>>(x);
  k_gemm<128,0><<<dim3(S_TOT/256, 6), 256>>>(wqkv, x, nullptr, g, b, nullptr);
  k_probes<<<256, 512>>>();
  k_kprobe_h<<<256, 512>>>();
  k_kprobe_w<<<256, 256>>>();
  k_gather<<<dim3(32, 8), 256>>>();
  cudaFuncSetAttribute((const void*)k_attn,
                       cudaFuncAttributeMaxDynamicSharedMemorySize, 65536);
  k_attn<<<dim3(S_TOT/256, 8), 256, 65536>>>();
  k_gemm<256,1><<<dim3(S_TOT/256, 1), 256>>>(wout, nullptr, out, nullptr, nullptr, bout);
}